// round 2
// baseline (speedup 1.0000x reference)
#include <cuda_runtime.h>
#include <math.h>

// Problem dims
#define BATCH 2048
#define HDIM  512
#define TSTEP 128
#define VDIM  64
#define GDIM  2048   // 4*HDIM

// ---------------- scratch (device globals; no allocation allowed) ----------
__device__ float g_xg[BATCH * GDIM];                       // 16 MB  x_gates
__device__ float g_h[2][BATCH * HDIM];                     // 2x4 MB h double buffer
__device__ float g_c[BATCH * HDIM];                        // 4 MB   cell state
__device__ float g_hs[(size_t)BATCH * TSTEP * HDIM];       // 512 MB all hidden states

// ---------------- packed f32x2 helpers (FFMA2 path, sm_100+) ---------------
typedef unsigned long long ull;

__device__ __forceinline__ ull ffma2(ull a, ull b, ull c) {
    ull d;
    asm("fma.rn.f32x2 %0, %1, %2, %3;" : "=l"(d) : "l"(a), "l"(b), "l"(c));
    return d;
}
__device__ __forceinline__ ull pk2(float x, float y) {
    ull r;
    asm("mov.b64 %0, {%1, %2};" : "=l"(r) : "f"(x), "f"(y));
    return r;
}
__device__ __forceinline__ float2 up2(ull v) {
    float2 r;
    asm("mov.b64 {%0, %1}, %2;" : "=f"(r.x), "=f"(r.y) : "l"(v));
    return r;
}

__device__ __forceinline__ float sigm(float x) {
    return 1.0f / (1.0f + __expf(-x));
}

// ---------------- init: zero h0 and c0 -------------------------------------
__global__ void init_kernel() {
    int i = blockIdx.x * blockDim.x + threadIdx.x;
    if (i < BATCH * HDIM) {
        g_h[0][i] = 0.0f;
        g_c[i]    = 0.0f;
    }
}

// ============================================================================
// Shared GEMM tiling (both pre_kernel and step_kernel):
//   block tile: BM=128 rows x BN=128 cols, BK=16, 256 threads
//   column mapping: n = g*32 + jj  ->  full col = g*512 + (blockIdx.y*32 + jj)
//   thread (tr=tid/16, tc=tid&15): rows tr*8..tr*8+7, col pairs jj0=tc*2 (+0,+1)
//   for all 4 gates g -> each thread owns complete (i,f,g,o) quads.
// ============================================================================

// -------- pre: x_gates = z @ w_ih.T + b_ih + b_hh ---------------------------
__global__ __launch_bounds__(256, 2)
void pre_kernel(const float* __restrict__ z,
                const float* __restrict__ w_ih,
                const float* __restrict__ b_ih,
                const float* __restrict__ b_hh) {
    __shared__ float As[16][132];
    __shared__ float Bs[16][130];

    const int bm = blockIdx.x;
    const int j0 = blockIdx.y * 32;
    const int tid = threadIdx.x;
    const int tr = tid >> 4, tc = tid & 15;
    const int jj0 = tc * 2;

    ull acc[8][4];
#pragma unroll
    for (int i = 0; i < 8; i++)
#pragma unroll
        for (int g = 0; g < 4; g++) acc[i][g] = 0ull;

    for (int k0 = 0; k0 < HDIM; k0 += 16) {
#pragma unroll
        for (int it = 0; it < 2; it++) {
            int i = tid + it * 256;
            int row = i >> 2, kq = (i & 3) * 4;
            float4 va = *(const float4*)(z + (size_t)(bm * 128 + row) * HDIM + k0 + kq);
            As[kq + 0][row] = va.x; As[kq + 1][row] = va.y;
            As[kq + 2][row] = va.z; As[kq + 3][row] = va.w;
            int n = row;
            int gcol = ((n >> 5) << 9) + j0 + (n & 31);
            float4 vb = *(const float4*)(w_ih + (size_t)gcol * HDIM + k0 + kq);
            Bs[kq + 0][n] = vb.x; Bs[kq + 1][n] = vb.y;
            Bs[kq + 2][n] = vb.z; Bs[kq + 3][n] = vb.w;
        }
        __syncthreads();
#pragma unroll
        for (int kk = 0; kk < 16; kk++) {
            float4 a0 = *(const float4*)&As[kk][tr * 8];
            float4 a1 = *(const float4*)&As[kk][tr * 8 + 4];
            ull b0 = *(const ull*)&Bs[kk][jj0];
            ull b1 = *(const ull*)&Bs[kk][32 + jj0];
            ull b2 = *(const ull*)&Bs[kk][64 + jj0];
            ull b3 = *(const ull*)&Bs[kk][96 + jj0];
            float av[8] = {a0.x, a0.y, a0.z, a0.w, a1.x, a1.y, a1.z, a1.w};
#pragma unroll
            for (int i = 0; i < 8; i++) {
                ull ad = pk2(av[i], av[i]);
                acc[i][0] = ffma2(ad, b0, acc[i][0]);
                acc[i][1] = ffma2(ad, b1, acc[i][1]);
                acc[i][2] = ffma2(ad, b2, acc[i][2]);
                acc[i][3] = ffma2(ad, b3, acc[i][3]);
            }
        }
        __syncthreads();
    }

    const int b0r = bm * 128 + tr * 8;
#pragma unroll
    for (int i = 0; i < 8; i++) {
        int b = b0r + i;
        float2 vv[4];
#pragma unroll
        for (int g = 0; g < 4; g++) vv[g] = up2(acc[i][g]);
#pragma unroll
        for (int g = 0; g < 4; g++) {
            int c0 = g * 512 + j0 + jj0;
            g_xg[(size_t)b * GDIM + c0]     = vv[g].x + b_ih[c0]     + b_hh[c0];
            g_xg[(size_t)b * GDIM + c0 + 1] = vv[g].y + b_ih[c0 + 1] + b_hh[c0 + 1];
        }
    }
}

// -------- step: gates = x_gates + h@w_hh.T ; fused LSTM cell ----------------
__global__ __launch_bounds__(256, 2)
void step_kernel(const float* __restrict__ w_hh, int t) {
    __shared__ float As[16][132];
    __shared__ float Bs[16][130];

    const float* __restrict__ h_in  = g_h[t & 1];
    float* __restrict__       h_out = g_h[(t & 1) ^ 1];

    const int bm = blockIdx.x;
    const int j0 = blockIdx.y * 32;
    const int tid = threadIdx.x;
    const int tr = tid >> 4, tc = tid & 15;
    const int jj0 = tc * 2;

    ull acc[8][4];
#pragma unroll
    for (int i = 0; i < 8; i++)
#pragma unroll
        for (int g = 0; g < 4; g++) acc[i][g] = 0ull;

    for (int k0 = 0; k0 < HDIM; k0 += 16) {
#pragma unroll
        for (int it = 0; it < 2; it++) {
            int i = tid + it * 256;
            int row = i >> 2, kq = (i & 3) * 4;
            float4 va = *(const float4*)(h_in + (size_t)(bm * 128 + row) * HDIM + k0 + kq);
            As[kq + 0][row] = va.x; As[kq + 1][row] = va.y;
            As[kq + 2][row] = va.z; As[kq + 3][row] = va.w;
            int n = row;
            int gcol = ((n >> 5) << 9) + j0 + (n & 31);
            float4 vb = *(const float4*)(w_hh + (size_t)gcol * HDIM + k0 + kq);
            Bs[kq + 0][n] = vb.x; Bs[kq + 1][n] = vb.y;
            Bs[kq + 2][n] = vb.z; Bs[kq + 3][n] = vb.w;
        }
        __syncthreads();
#pragma unroll
        for (int kk = 0; kk < 16; kk++) {
            float4 a0 = *(const float4*)&As[kk][tr * 8];
            float4 a1 = *(const float4*)&As[kk][tr * 8 + 4];
            ull b0 = *(const ull*)&Bs[kk][jj0];
            ull b1 = *(const ull*)&Bs[kk][32 + jj0];
            ull b2 = *(const ull*)&Bs[kk][64 + jj0];
            ull b3 = *(const ull*)&Bs[kk][96 + jj0];
            float av[8] = {a0.x, a0.y, a0.z, a0.w, a1.x, a1.y, a1.z, a1.w};
#pragma unroll
            for (int i = 0; i < 8; i++) {
                ull ad = pk2(av[i], av[i]);
                acc[i][0] = ffma2(ad, b0, acc[i][0]);
                acc[i][1] = ffma2(ad, b1, acc[i][1]);
                acc[i][2] = ffma2(ad, b2, acc[i][2]);
                acc[i][3] = ffma2(ad, b3, acc[i][3]);
            }
        }
        __syncthreads();
    }

    // fused LSTM cell epilogue
    const int b0r = bm * 128 + tr * 8;
#pragma unroll
    for (int i = 0; i < 8; i++) {
        int b = b0r + i;
        float2 vi = up2(acc[i][0]);
        float2 vf = up2(acc[i][1]);
        float2 vg = up2(acc[i][2]);
        float2 vo = up2(acc[i][3]);
#pragma unroll
        for (int p = 0; p < 2; p++) {
            int hcol = j0 + jj0 + p;
            const float* xgp = g_xg + (size_t)b * GDIM + hcol;
            float gi = (p ? vi.y : vi.x) + xgp[0];
            float gf = (p ? vf.y : vf.x) + xgp[512];
            float gg = (p ? vg.y : vg.x) + xgp[1024];
            float go = (p ? vo.y : vo.x) + xgp[1536];
            int idx = b * HDIM + hcol;
            float cn = sigm(gf) * g_c[idx] + sigm(gi) * tanhf(gg);
            g_c[idx] = cn;
            float hn = sigm(go) * tanhf(cn);
            h_out[idx] = hn;
            g_hs[((size_t)b * TSTEP + t) * HDIM + hcol] = hn;
        }
    }
}

// -------- fc: out = relu(hs @ fc_w.T + fc_b) --------------------------------
__global__ __launch_bounds__(256)
void fc_kernel(const float* __restrict__ fc_w,
               const float* __restrict__ fc_b,
               float* __restrict__ out) {
    __shared__ float hsS[16][514];   // pad 2 -> conflict-free column reads
    const size_t row0 = (size_t)blockIdx.x * 16;
    const int tid = threadIdx.x;

    // stage 16 rows (b,t) of hs
#pragma unroll
    for (int it = 0; it < 16; it++) {
        int i = tid + it * 256;
        int row = i >> 8;
        int cc = (i & 255) * 2;
        float2 v = *(const float2*)(g_hs + (row0 + row) * HDIM + cc);
        *(float2*)&hsS[row][cc] = v;
    }
    __syncthreads();

    const int r = tid & 15;
    const int v0 = (tid >> 4) * 4;
    ull acc[4] = {0ull, 0ull, 0ull, 0ull};
    const float* w0 = fc_w + (size_t)v0 * HDIM;

#pragma unroll 8
    for (int k = 0; k < HDIM; k += 2) {
        ull a = *(const ull*)&hsS[r][k];
        acc[0] = ffma2(a, *(const ull*)(w0 + k),        acc[0]);
        acc[1] = ffma2(a, *(const ull*)(w0 + 512 + k),  acc[1]);
        acc[2] = ffma2(a, *(const ull*)(w0 + 1024 + k), acc[2]);
        acc[3] = ffma2(a, *(const ull*)(w0 + 1536 + k), acc[3]);
    }
#pragma unroll
    for (int j = 0; j < 4; j++) {
        float2 s = up2(acc[j]);
        float v = s.x + s.y + fc_b[v0 + j];
        out[(row0 + r) * VDIM + v0 + j] = fmaxf(v, 0.0f);
    }
}

// ---------------- launch ----------------------------------------------------
extern "C" void kernel_launch(void* const* d_in, const int* in_sizes, int n_in,
                              void* d_out, int out_size) {
    const float* z    = (const float*)d_in[0];
    const float* w_ih = (const float*)d_in[1];
    const float* w_hh = (const float*)d_in[2];
    const float* b_ih = (const float*)d_in[3];
    const float* b_hh = (const float*)d_in[4];
    const float* fc_w = (const float*)d_in[5];
    const float* fc_b = (const float*)d_in[6];
    float* out = (float*)d_out;

    init_kernel<<<(BATCH * HDIM + 255) / 256, 256>>>();
    pre_kernel<<<dim3(16, 16), 256>>>(z, w_ih, b_ih, b_hh);
    for (int t = 0; t < TSTEP; t++) {
        step_kernel<<<dim3(16, 16), 256>>>(w_hh, t);
    }
    fc_kernel<<<(BATCH * TSTEP) / 16, 256>>>(fc_w, fc_b, out);
}

// round 5
// speedup vs baseline: 1.9392x; 1.9392x over previous
#include <cuda_runtime.h>
#include <cuda_bf16.h>
#include <cstdint>
#include <math.h>

// Problem dims
#define BATCH 2048
#define HDIM  512
#define TSTEP 128
#define VDIM  64
#define GDIM  2048   // 4*HDIM

// ---------------- scratch (device globals; no allocation allowed) ----------
__device__ float g_xg[BATCH * GDIM];                         // 16 MB  x_gates
__device__ float g_c[BATCH * HDIM];                          // 4 MB   cell state
__device__ float g_hs[(size_t)BATCH * TSTEP * HDIM];         // 512 MB hidden states (fp32)
// h as bf16 split, double buffered by t parity
__device__ __nv_bfloat16 g_hAhi[2][BATCH * HDIM];
__device__ __nv_bfloat16 g_hAlo[2][BATCH * HDIM];
// w_hh rearranged per N-block (by): [8][256 rows][512 k], row r -> orig (r>>6)*512 + by*64 + (r&63)
__device__ __nv_bfloat16 g_wBhi[8][256 * HDIM];
__device__ __nv_bfloat16 g_wBlo[8][256 * HDIM];

// ---------------- packed f32x2 helpers (FFMA2 path) -------------------------
typedef unsigned long long ull;

__device__ __forceinline__ ull ffma2(ull a, ull b, ull c) {
    ull d;
    asm("fma.rn.f32x2 %0, %1, %2, %3;" : "=l"(d) : "l"(a), "l"(b), "l"(c));
    return d;
}
__device__ __forceinline__ ull pk2(float x, float y) {
    ull r;
    asm("mov.b64 %0, {%1, %2};" : "=l"(r) : "f"(x), "f"(y));
    return r;
}
__device__ __forceinline__ float2 up2(ull v) {
    float2 r;
    asm("mov.b64 {%0, %1}, %2;" : "=f"(r.x), "=f"(r.y) : "l"(v));
    return r;
}

__device__ __forceinline__ float sigm(float x) {
    return 1.0f / (1.0f + __expf(-x));
}
__device__ __forceinline__ float tanh_fast(float x) {
    float e = __expf(-2.0f * fabsf(x));
    float r = (1.0f - e) / (1.0f + e);
    return copysignf(r, x);
}

// ---------------- mma.sync / ldmatrix / cp.async helpers --------------------
__device__ __forceinline__ uint32_t smem_u32(const void* p) {
    uint32_t a;
    asm("{ .reg .u64 t; cvta.to.shared.u64 t, %1; cvt.u32.u64 %0, t; }" : "=r"(a) : "l"(p));
    return a;
}
__device__ __forceinline__ void ldsm_x4(uint32_t* r, uint32_t addr) {
    asm volatile("ldmatrix.sync.aligned.m8n8.x4.shared.b16 {%0,%1,%2,%3}, [%4];"
                 : "=r"(r[0]), "=r"(r[1]), "=r"(r[2]), "=r"(r[3]) : "r"(addr));
}
__device__ __forceinline__ void mma16816(float* d, const uint32_t* a, const uint32_t* b) {
    asm volatile("mma.sync.aligned.m16n8k16.row.col.f32.bf16.bf16.f32 "
                 "{%0,%1,%2,%3}, {%4,%5,%6,%7}, {%8,%9}, {%0,%1,%2,%3};"
                 : "+f"(d[0]), "+f"(d[1]), "+f"(d[2]), "+f"(d[3])
                 : "r"(a[0]), "r"(a[1]), "r"(a[2]), "r"(a[3]), "r"(b[0]), "r"(b[1]));
}
__device__ __forceinline__ void cpa16(uint32_t dst, const void* src) {
    asm volatile("cp.async.cg.shared.global [%0], [%1], 16;"
                 :: "r"(dst), "l"(__cvta_generic_to_global(src)) : "memory");
}
#define CPA_COMMIT() asm volatile("cp.async.commit_group;" ::: "memory")
#define CPA_WAIT0()  asm volatile("cp.async.wait_group 0;" ::: "memory")

// ---------------- init: zero c and h0 splits --------------------------------
__global__ void init_kernel() {
    int i = blockIdx.x * blockDim.x + threadIdx.x;
    if (i < BATCH * HDIM) {
        g_c[i] = 0.0f;
        g_hAhi[0][i] = __float2bfloat16(0.0f);
        g_hAlo[0][i] = __float2bfloat16(0.0f);
    }
}

// ---------------- wprep: decompose + rearrange w_hh --------------------------
__global__ void wprep_kernel(const float* __restrict__ w_hh) {
    int i = blockIdx.x * blockDim.x + threadIdx.x;   // over 8*256*512
    if (i >= 8 * 256 * HDIM) return;
    int k = i & (HDIM - 1);
    int r = (i >> 9) & 255;
    int by = i >> 17;
    int orig_row = ((r >> 6) << 9) + by * 64 + (r & 63);
    float w = w_hh[(size_t)orig_row * HDIM + k];
    __nv_bfloat16 hi = __float2bfloat16_rn(w);
    float rem = w - __bfloat162float(hi);
    g_wBhi[by][r * HDIM + k] = hi;
    g_wBlo[by][r * HDIM + k] = __float2bfloat16_rn(rem);
}

// -------- pre: x_gates = z @ w_ih.T + b_ih + b_hh (FFMA2, one-time) ----------
__global__ __launch_bounds__(256, 2)
void pre_kernel(const float* __restrict__ z,
                const float* __restrict__ w_ih,
                const float* __restrict__ b_ih,
                const float* __restrict__ b_hh) {
    __shared__ float As[16][132];
    __shared__ float Bs[16][130];

    const int bm = blockIdx.x;
    const int j0 = blockIdx.y * 32;
    const int tid = threadIdx.x;
    const int tr = tid >> 4, tc = tid & 15;
    const int jj0 = tc * 2;

    ull acc[8][4];
#pragma unroll
    for (int i = 0; i < 8; i++)
#pragma unroll
        for (int g = 0; g < 4; g++) acc[i][g] = 0ull;

    for (int k0 = 0; k0 < HDIM; k0 += 16) {
#pragma unroll
        for (int it = 0; it < 2; it++) {
            int i = tid + it * 256;
            int row = i >> 2, kq = (i & 3) * 4;
            float4 va = *(const float4*)(z + (size_t)(bm * 128 + row) * HDIM + k0 + kq);
            As[kq + 0][row] = va.x; As[kq + 1][row] = va.y;
            As[kq + 2][row] = va.z; As[kq + 3][row] = va.w;
            int n = row;
            int gcol = ((n >> 5) << 9) + j0 + (n & 31);
            float4 vb = *(const float4*)(w_ih + (size_t)gcol * HDIM + k0 + kq);
            Bs[kq + 0][n] = vb.x; Bs[kq + 1][n] = vb.y;
            Bs[kq + 2][n] = vb.z; Bs[kq + 3][n] = vb.w;
        }
        __syncthreads();
#pragma unroll
        for (int kk = 0; kk < 16; kk++) {
            float4 a0 = *(const float4*)&As[kk][tr * 8];
            float4 a1 = *(const float4*)&As[kk][tr * 8 + 4];
            ull b0 = *(const ull*)&Bs[kk][jj0];
            ull b1 = *(const ull*)&Bs[kk][32 + jj0];
            ull b2 = *(const ull*)&Bs[kk][64 + jj0];
            ull b3 = *(const ull*)&Bs[kk][96 + jj0];
            float av[8] = {a0.x, a0.y, a0.z, a0.w, a1.x, a1.y, a1.z, a1.w};
#pragma unroll
            for (int i = 0; i < 8; i++) {
                ull ad = pk2(av[i], av[i]);
                acc[i][0] = ffma2(ad, b0, acc[i][0]);
                acc[i][1] = ffma2(ad, b1, acc[i][1]);
                acc[i][2] = ffma2(ad, b2, acc[i][2]);
                acc[i][3] = ffma2(ad, b3, acc[i][3]);
            }
        }
        __syncthreads();
    }

    const int b0r = bm * 128 + tr * 8;
#pragma unroll
    for (int i = 0; i < 8; i++) {
        int b = b0r + i;
        float2 vv[4];
#pragma unroll
        for (int g = 0; g < 4; g++) vv[g] = up2(acc[i][g]);
#pragma unroll
        for (int g = 0; g < 4; g++) {
            int c0 = g * 512 + j0 + jj0;
            g_xg[(size_t)b * GDIM + c0]     = vv[g].x + b_ih[c0]     + b_hh[c0];
            g_xg[(size_t)b * GDIM + c0 + 1] = vv[g].y + b_ih[c0 + 1] + b_hh[c0 + 1];
        }
    }
}

// ============================================================================
// step_mma: gates = x_gates + h@w_hh.T via mma.sync bf16 3-pass split
//   grid (16, 8), 512 threads. CTA tile M=128 x N=256 (n = g*64 + hcol).
//   K=512 in 16 chunks of 32, cp.async double buffer, ldmatrix + swizzle.
// ============================================================================
#define KCH 32
#define AH_OFF 0
#define AL_OFF 8192
#define BH_OFF 16384
#define BL_OFF 32768
#define BUFSZ  49152
#define EPI_STRIDE 264
#define SMEM_TOTAL (128 * EPI_STRIDE * 4)   // 135168 >= 2*BUFSZ (98304)

__global__ __launch_bounds__(512, 1)
void step_mma(int t) {
    extern __shared__ char smem[];
    const uint32_t smem_base = smem_u32(smem);
    float* E = (float*)smem;

    const int tid = threadIdx.x;
    const int wid = tid >> 5;
    const int lid = tid & 31;
    const int bm = blockIdx.x;
    const int by = blockIdx.y;

    const __nv_bfloat16* __restrict__ hin_hi = g_hAhi[t & 1];
    const __nv_bfloat16* __restrict__ hin_lo = g_hAlo[t & 1];
    __nv_bfloat16* __restrict__ hout_hi = g_hAhi[(t & 1) ^ 1];
    __nv_bfloat16* __restrict__ hout_lo = g_hAlo[(t & 1) ^ 1];
    const __nv_bfloat16* __restrict__ wb_hi = g_wBhi[by];
    const __nv_bfloat16* __restrict__ wb_lo = g_wBlo[by];

    // ---- per-thread cp.async source/dest precompute ----
    // A: 512 16B-units (128 rows x 4 units), one per thread
    const int arow = tid >> 2, au = tid & 3;
    const uint32_t a_dst = smem_base + arow * 64 + ((au ^ (arow & 3)) * 16);
    const size_t a_src = (size_t)(bm * 128 + arow) * HDIM + au * 8;
    // B: 1024 units, two per thread
    const int brow0 = tid >> 2, bu0 = tid & 3;
    const int brow1 = (tid + 512) >> 2, bu1 = tid & 3;
    const uint32_t b_dst0 = smem_base + BH_OFF + brow0 * 64 + ((bu0 ^ (brow0 & 3)) * 16);
    const uint32_t b_dst1 = smem_base + BH_OFF + brow1 * 64 + ((bu1 ^ (brow1 & 3)) * 16);
    const size_t b_src0 = (size_t)brow0 * HDIM + bu0 * 8;
    const size_t b_src1 = (size_t)brow1 * HDIM + bu1 * 8;

    // ---- ldmatrix lane address offsets (s=0; s=1 -> XOR 32) ----
    const int warp_m = wid >> 2;           // 0..3 -> m base warp_m*32
    const int warp_n = wid & 3;            // 0..3 -> n base warp_n*64
    uint32_t a_off[2], b_off[4];
    {
        int j = lid >> 3;
        int r0 = warp_m * 32 + (lid & 7) + ((j & 1) << 3);
        int kh = j >> 1;
#pragma unroll
        for (int i = 0; i < 2; i++) {
            int row = r0 + i * 16;
            a_off[i] = row * 64 + ((kh ^ (row & 3)) * 16);
        }
        int rb0 = warp_n * 64 + (lid & 7) + ((j >> 1) << 3);
        int bkh = j & 1;
#pragma unroll
        for (int q = 0; q < 4; q++) {
            int row = rb0 + q * 16;
            b_off[q] = row * 64 + ((bkh ^ (row & 3)) * 16);
        }
    }

    float acc[2][8][4];
#pragma unroll
    for (int i = 0; i < 2; i++)
#pragma unroll
        for (int f = 0; f < 8; f++)
#pragma unroll
            for (int v = 0; v < 4; v++) acc[i][f][v] = 0.0f;

    // ---- prologue: load chunk 0 ----
    {
        uint32_t d = a_dst;
        cpa16(d, hin_hi + a_src);
        cpa16(d + AL_OFF, hin_lo + a_src);
        cpa16(b_dst0, wb_hi + b_src0);
        cpa16(b_dst0 + (BL_OFF - BH_OFF), wb_lo + b_src0);
        cpa16(b_dst1, wb_hi + b_src1);
        cpa16(b_dst1 + (BL_OFF - BH_OFF), wb_lo + b_src1);
        CPA_COMMIT();
    }
    CPA_WAIT0();
    __syncthreads();

    for (int c = 0; c < 16; c++) {
        // prefetch next chunk into the other buffer
        if (c < 15) {
            const uint32_t bo = ((c + 1) & 1) * BUFSZ;
            const size_t ko = (size_t)(c + 1) * KCH;
            cpa16(a_dst + bo, hin_hi + a_src + ko);
            cpa16(a_dst + bo + AL_OFF, hin_lo + a_src + ko);
            cpa16(b_dst0 + bo, wb_hi + b_src0 + ko);
            cpa16(b_dst0 + bo + (BL_OFF - BH_OFF), wb_lo + b_src0 + ko);
            cpa16(b_dst1 + bo, wb_hi + b_src1 + ko);
            cpa16(b_dst1 + bo + (BL_OFF - BH_OFF), wb_lo + b_src1 + ko);
            CPA_COMMIT();
        }

        const uint32_t base = smem_base + (c & 1) * BUFSZ;
#pragma unroll
        for (int s = 0; s < 2; s++) {
            const uint32_t sx = s ? 32u : 0u;
            uint32_t ah[2][4], al[2][4], bb[4][4];
            // A hi + B hi
#pragma unroll
            for (int i = 0; i < 2; i++) ldsm_x4(ah[i], base + AH_OFF + (a_off[i] ^ sx));
#pragma unroll
            for (int q = 0; q < 4; q++) ldsm_x4(bb[q], base + BH_OFF + (b_off[q] ^ sx));
            // pass hh
#pragma unroll
            for (int i = 0; i < 2; i++)
#pragma unroll
                for (int f = 0; f < 8; f++)
                    mma16816(acc[i][f], ah[i], &bb[f >> 1][(f & 1) * 2]);
            // A lo, pass lh (B hi still live)
#pragma unroll
            for (int i = 0; i < 2; i++) ldsm_x4(al[i], base + AL_OFF + (a_off[i] ^ sx));
#pragma unroll
            for (int i = 0; i < 2; i++)
#pragma unroll
                for (int f = 0; f < 8; f++)
                    mma16816(acc[i][f], al[i], &bb[f >> 1][(f & 1) * 2]);
            // B lo (reuse bb regs), pass hl
#pragma unroll
            for (int q = 0; q < 4; q++) ldsm_x4(bb[q], base + BL_OFF + (b_off[q] ^ sx));
#pragma unroll
            for (int i = 0; i < 2; i++)
#pragma unroll
                for (int f = 0; f < 8; f++)
                    mma16816(acc[i][f], ah[i], &bb[f >> 1][(f & 1) * 2]);
        }

        if (c < 15) {
            CPA_WAIT0();
            __syncthreads();
        }
    }

    // ---- stage accumulators to smem (overwrites dead operand buffers) ----
    __syncthreads();
    {
        const int r0 = warp_m * 32 + (lid >> 2);
        const int c0 = warp_n * 64 + (lid & 3) * 2;
#pragma unroll
        for (int i = 0; i < 2; i++)
#pragma unroll
            for (int f = 0; f < 8; f++) {
                int r = r0 + i * 16;
                int cc = c0 + f * 8;
                *(float2*)&E[r * EPI_STRIDE + cc]       = make_float2(acc[i][f][0], acc[i][f][1]);
                *(float2*)&E[(r + 8) * EPI_STRIDE + cc] = make_float2(acc[i][f][2], acc[i][f][3]);
            }
    }
    __syncthreads();

    // ---- fused LSTM cell epilogue ----
    {
        const int hcol = tid & 63;
        const int mb = (tid >> 6) * 16;
        const int hcol_g = by * 64 + hcol;
#pragma unroll 4
        for (int j = 0; j < 16; j++) {
            const int m = mb + j;
            const int b = bm * 128 + m;
            const float* xg = g_xg + (size_t)b * GDIM + hcol_g;
            float gi = E[m * EPI_STRIDE + hcol]       + xg[0];
            float gf = E[m * EPI_STRIDE + 64 + hcol]  + xg[512];
            float gg = E[m * EPI_STRIDE + 128 + hcol] + xg[1024];
            float go = E[m * EPI_STRIDE + 192 + hcol] + xg[1536];
            const size_t ci = (size_t)b * HDIM + hcol_g;
            float cn = sigm(gf) * g_c[ci] + sigm(gi) * tanh_fast(gg);
            g_c[ci] = cn;
            float hn = sigm(go) * tanh_fast(cn);
            g_hs[((size_t)b * TSTEP + t) * HDIM + hcol_g] = hn;
            __nv_bfloat16 hb = __float2bfloat16_rn(hn);
            float rem = hn - __bfloat162float(hb);
            hout_hi[ci] = hb;
            hout_lo[ci] = __float2bfloat16_rn(rem);
        }
    }
}

// -------- fc: out = relu(hs @ fc_w.T + fc_b) --------------------------------
__global__ __launch_bounds__(256)
void fc_kernel(const float* __restrict__ fc_w,
               const float* __restrict__ fc_b,
               float* __restrict__ out) {
    __shared__ float hsS[16][514];
    const size_t row0 = (size_t)blockIdx.x * 16;
    const int tid = threadIdx.x;

#pragma unroll
    for (int it = 0; it < 16; it++) {
        int i = tid + it * 256;
        int row = i >> 8;
        int cc = (i & 255) * 2;
        float2 v = *(const float2*)(g_hs + (row0 + row) * HDIM + cc);
        *(float2*)&hsS[row][cc] = v;
    }
    __syncthreads();

    const int r = tid & 15;
    const int v0 = (tid >> 4) * 4;
    ull acc[4] = {0ull, 0ull, 0ull, 0ull};
    const float* w0 = fc_w + (size_t)v0 * HDIM;

#pragma unroll 8
    for (int k = 0; k < HDIM; k += 2) {
        ull a = *(const ull*)&hsS[r][k];
        acc[0] = ffma2(a, *(const ull*)(w0 + k),        acc[0]);
        acc[1] = ffma2(a, *(const ull*)(w0 + 512 + k),  acc[1]);
        acc[2] = ffma2(a, *(const ull*)(w0 + 1024 + k), acc[2]);
        acc[3] = ffma2(a, *(const ull*)(w0 + 1536 + k), acc[3]);
    }
#pragma unroll
    for (int j = 0; j < 4; j++) {
        float2 s = up2(acc[j]);
        float v = s.x + s.y + fc_b[v0 + j];
        out[(row0 + r) * VDIM + v0 + j] = fmaxf(v, 0.0f);
    }
}

// ---------------- launch ----------------------------------------------------
extern "C" void kernel_launch(void* const* d_in, const int* in_sizes, int n_in,
                              void* d_out, int out_size) {
    const float* z    = (const float*)d_in[0];
    const float* w_ih = (const float*)d_in[1];
    const float* w_hh = (const float*)d_in[2];
    const float* b_ih = (const float*)d_in[3];
    const float* b_hh = (const float*)d_in[4];
    const float* fc_w = (const float*)d_in[5];
    const float* fc_b = (const float*)d_in[6];
    float* out = (float*)d_out;

    cudaFuncSetAttribute(step_mma, cudaFuncAttributeMaxDynamicSharedMemorySize, SMEM_TOTAL);

    init_kernel<<<(BATCH * HDIM + 255) / 256, 256>>>();
    wprep_kernel<<<(8 * 256 * HDIM + 255) / 256, 256>>>(w_hh);
    pre_kernel<<<dim3(16, 16), 256>>>(z, w_ih, b_ih, b_hh);
    for (int t = 0; t < TSTEP; t++) {
        step_mma<<<dim3(16, 8), 512, SMEM_TOTAL>>>(t);
    }
    fc_kernel<<<(BATCH * TSTEP) / 16, 256>>>(fc_w, fc_b, out);
}

// round 6
// speedup vs baseline: 1.9409x; 1.0009x over previous
#include <cuda_runtime.h>
#include <cuda_bf16.h>
#include <cstdint>
#include <math.h>

// Problem dims
#define BATCH 2048
#define HDIM  512
#define TSTEP 128
#define VDIM  64
#define GDIM  2048   // 4*HDIM

// ---------------- scratch (device globals; no allocation allowed) ----------
__device__ float g_xg[BATCH * GDIM];                         // 16 MB  x_gates
__device__ float g_c[BATCH * HDIM];                          // 4 MB   cell state
__device__ float g_hs[(size_t)BATCH * TSTEP * HDIM];         // 512 MB hidden states (fp32)
// h as bf16 split, double buffered by t parity
__device__ __nv_bfloat16 g_hAhi[2][BATCH * HDIM];
__device__ __nv_bfloat16 g_hAlo[2][BATCH * HDIM];
// w_hh rearranged per N-block (by): [16][128 rows][512 k], row r -> orig (r>>5)*512 + by*32 + (r&31)
__device__ __nv_bfloat16 g_wBhi[16][128 * HDIM];
__device__ __nv_bfloat16 g_wBlo[16][128 * HDIM];

// ---------------- packed f32x2 helpers (FFMA2 path) -------------------------
typedef unsigned long long ull;

__device__ __forceinline__ ull ffma2(ull a, ull b, ull c) {
    ull d;
    asm("fma.rn.f32x2 %0, %1, %2, %3;" : "=l"(d) : "l"(a), "l"(b), "l"(c));
    return d;
}
__device__ __forceinline__ ull pk2(float x, float y) {
    ull r;
    asm("mov.b64 %0, {%1, %2};" : "=l"(r) : "f"(x), "f"(y));
    return r;
}
__device__ __forceinline__ float2 up2(ull v) {
    float2 r;
    asm("mov.b64 {%0, %1}, %2;" : "=f"(r.x), "=f"(r.y) : "l"(v));
    return r;
}

__device__ __forceinline__ float sigm(float x) {
    return 1.0f / (1.0f + __expf(-x));
}
__device__ __forceinline__ float tanh_fast(float x) {
    float e = __expf(-2.0f * fabsf(x));
    float r = (1.0f - e) / (1.0f + e);
    return copysignf(r, x);
}

// ---------------- mma.sync / ldmatrix / cp.async helpers --------------------
__device__ __forceinline__ uint32_t smem_u32(const void* p) {
    uint32_t a;
    asm("{ .reg .u64 t; cvta.to.shared.u64 t, %1; cvt.u32.u64 %0, t; }" : "=r"(a) : "l"(p));
    return a;
}
__device__ __forceinline__ void ldsm_x4(uint32_t* r, uint32_t addr) {
    asm volatile("ldmatrix.sync.aligned.m8n8.x4.shared.b16 {%0,%1,%2,%3}, [%4];"
                 : "=r"(r[0]), "=r"(r[1]), "=r"(r[2]), "=r"(r[3]) : "r"(addr));
}
__device__ __forceinline__ void mma16816(float* d, const uint32_t* a, const uint32_t* b) {
    asm volatile("mma.sync.aligned.m16n8k16.row.col.f32.bf16.bf16.f32 "
                 "{%0,%1,%2,%3}, {%4,%5,%6,%7}, {%8,%9}, {%0,%1,%2,%3};"
                 : "+f"(d[0]), "+f"(d[1]), "+f"(d[2]), "+f"(d[3])
                 : "r"(a[0]), "r"(a[1]), "r"(a[2]), "r"(a[3]), "r"(b[0]), "r"(b[1]));
}
__device__ __forceinline__ void cpa16(uint32_t dst, const void* src) {
    asm volatile("cp.async.cg.shared.global [%0], [%1], 16;"
                 :: "r"(dst), "l"(__cvta_generic_to_global(src)) : "memory");
}
#define CPA_COMMIT() asm volatile("cp.async.commit_group;" ::: "memory")
#define CPA_WAIT0()  asm volatile("cp.async.wait_group 0;" ::: "memory")
#define CPA_WAIT1()  asm volatile("cp.async.wait_group 1;" ::: "memory")

// ---------------- init: zero c and h0 splits --------------------------------
__global__ void init_kernel() {
    int i = blockIdx.x * blockDim.x + threadIdx.x;
    if (i < BATCH * HDIM) {
        g_c[i] = 0.0f;
        g_hAhi[0][i] = __float2bfloat16(0.0f);
        g_hAlo[0][i] = __float2bfloat16(0.0f);
    }
}

// ---------------- wprep: decompose + rearrange w_hh --------------------------
__global__ void wprep_kernel(const float* __restrict__ w_hh) {
    int i = blockIdx.x * blockDim.x + threadIdx.x;   // over 16*128*512
    if (i >= 16 * 128 * HDIM) return;
    int k = i & (HDIM - 1);
    int r = (i >> 9) & 127;
    int by = i >> 16;
    int orig_row = ((r >> 5) << 9) + by * 32 + (r & 31);
    float w = w_hh[(size_t)orig_row * HDIM + k];
    __nv_bfloat16 hi = __float2bfloat16_rn(w);
    float rem = w - __bfloat162float(hi);
    g_wBhi[by][r * HDIM + k] = hi;
    g_wBlo[by][r * HDIM + k] = __float2bfloat16_rn(rem);
}

// -------- pre: x_gates = z @ w_ih.T + b_ih + b_hh (FFMA2, one-time) ----------
__global__ __launch_bounds__(256, 2)
void pre_kernel(const float* __restrict__ z,
                const float* __restrict__ w_ih,
                const float* __restrict__ b_ih,
                const float* __restrict__ b_hh) {
    __shared__ float As[16][132];
    __shared__ float Bs[16][130];

    const int bm = blockIdx.x;
    const int j0 = blockIdx.y * 32;
    const int tid = threadIdx.x;
    const int tr = tid >> 4, tc = tid & 15;
    const int jj0 = tc * 2;

    ull acc[8][4];
#pragma unroll
    for (int i = 0; i < 8; i++)
#pragma unroll
        for (int g = 0; g < 4; g++) acc[i][g] = 0ull;

    for (int k0 = 0; k0 < HDIM; k0 += 16) {
#pragma unroll
        for (int it = 0; it < 2; it++) {
            int i = tid + it * 256;
            int row = i >> 2, kq = (i & 3) * 4;
            float4 va = *(const float4*)(z + (size_t)(bm * 128 + row) * HDIM + k0 + kq);
            As[kq + 0][row] = va.x; As[kq + 1][row] = va.y;
            As[kq + 2][row] = va.z; As[kq + 3][row] = va.w;
            int n = row;
            int gcol = ((n >> 5) << 9) + j0 + (n & 31);
            float4 vb = *(const float4*)(w_ih + (size_t)gcol * HDIM + k0 + kq);
            Bs[kq + 0][n] = vb.x; Bs[kq + 1][n] = vb.y;
            Bs[kq + 2][n] = vb.z; Bs[kq + 3][n] = vb.w;
        }
        __syncthreads();
#pragma unroll
        for (int kk = 0; kk < 16; kk++) {
            float4 a0 = *(const float4*)&As[kk][tr * 8];
            float4 a1 = *(const float4*)&As[kk][tr * 8 + 4];
            ull b0 = *(const ull*)&Bs[kk][jj0];
            ull b1 = *(const ull*)&Bs[kk][32 + jj0];
            ull b2 = *(const ull*)&Bs[kk][64 + jj0];
            ull b3 = *(const ull*)&Bs[kk][96 + jj0];
            float av[8] = {a0.x, a0.y, a0.z, a0.w, a1.x, a1.y, a1.z, a1.w};
#pragma unroll
            for (int i = 0; i < 8; i++) {
                ull ad = pk2(av[i], av[i]);
                acc[i][0] = ffma2(ad, b0, acc[i][0]);
                acc[i][1] = ffma2(ad, b1, acc[i][1]);
                acc[i][2] = ffma2(ad, b2, acc[i][2]);
                acc[i][3] = ffma2(ad, b3, acc[i][3]);
            }
        }
        __syncthreads();
    }

    const int b0r = bm * 128 + tr * 8;
#pragma unroll
    for (int i = 0; i < 8; i++) {
        int b = b0r + i;
        float2 vv[4];
#pragma unroll
        for (int g = 0; g < 4; g++) vv[g] = up2(acc[i][g]);
#pragma unroll
        for (int g = 0; g < 4; g++) {
            int c0 = g * 512 + j0 + jj0;
            g_xg[(size_t)b * GDIM + c0]     = vv[g].x + b_ih[c0]     + b_hh[c0];
            g_xg[(size_t)b * GDIM + c0 + 1] = vv[g].y + b_ih[c0 + 1] + b_hh[c0 + 1];
        }
    }
}

// ============================================================================
// step_mma: gates = x_gates + h@w_hh.T via mma.sync bf16 3-pass split
//   grid (16, 16), 256 threads (8 warps), 2 CTAs/SM.
//   CTA tile M=128 x N=128 (n = g*32 + hcol), warp tile M64 x N32.
//   K=512 in 16 chunks of 32, cp.async TRIPLE buffer (wait_group 1).
// ============================================================================
#define KCH 32
#define AH_OFF 0
#define AL_OFF 8192
#define BH_OFF 16384
#define BL_OFF 24576
#define BUFSZ  32768
#define NBUF   3
#define EPI_STRIDE 132
#define SMEM_TOTAL (NBUF * BUFSZ)   // 98304 >= epi 128*132*4 = 67584

__global__ __launch_bounds__(256, 2)
void step_mma(int t) {
    extern __shared__ char smem[];
    const uint32_t smem_base = smem_u32(smem);
    float* E = (float*)smem;

    const int tid = threadIdx.x;
    const int wid = tid >> 5;
    const int lid = tid & 31;
    const int bm = blockIdx.x;
    const int by = blockIdx.y;

    const __nv_bfloat16* __restrict__ hin_hi = g_hAhi[t & 1];
    const __nv_bfloat16* __restrict__ hin_lo = g_hAlo[t & 1];
    __nv_bfloat16* __restrict__ hout_hi = g_hAhi[(t & 1) ^ 1];
    __nv_bfloat16* __restrict__ hout_lo = g_hAlo[(t & 1) ^ 1];
    const __nv_bfloat16* __restrict__ wb_hi = g_wBhi[by];
    const __nv_bfloat16* __restrict__ wb_lo = g_wBlo[by];

    // ---- cp.async addressing: 128 rows x 4 units per tile, 2 units/thread ----
    const int r0 = tid >> 2, u = tid & 3;
    const int r1 = r0 + 64;
    const uint32_t d0 = smem_base + r0 * 64 + ((u ^ (r0 & 3)) * 16);
    const uint32_t d1 = smem_base + r1 * 64 + ((u ^ (r1 & 3)) * 16);
    const size_t a_src0 = (size_t)(bm * 128 + r0) * HDIM + u * 8;
    const size_t a_src1 = (size_t)(bm * 128 + r1) * HDIM + u * 8;
    const size_t b_src0 = (size_t)r0 * HDIM + u * 8;
    const size_t b_src1 = (size_t)r1 * HDIM + u * 8;

    // ---- ldmatrix lane address offsets (s=0; s=1 -> XOR 32) ----
    const int warp_m = wid >> 2;           // 0..1 -> m base warp_m*64
    const int warp_n = wid & 3;            // 0..3 -> n base warp_n*32
    uint32_t a_off[4], b_off[2];
    {
        int j = lid >> 3;
        int ra = warp_m * 64 + (lid & 7) + ((j & 1) << 3);
        int kh = j >> 1;
#pragma unroll
        for (int i = 0; i < 4; i++) {
            int row = ra + i * 16;
            a_off[i] = row * 64 + ((kh ^ (row & 3)) * 16);
        }
        int rb = warp_n * 32 + (lid & 7) + ((j >> 1) << 3);
        int bkh = j & 1;
#pragma unroll
        for (int q = 0; q < 2; q++) {
            int row = rb + q * 16;
            b_off[q] = row * 64 + ((bkh ^ (row & 3)) * 16);
        }
    }

    float acc[4][4][4];
#pragma unroll
    for (int i = 0; i < 4; i++)
#pragma unroll
        for (int f = 0; f < 4; f++)
#pragma unroll
            for (int v = 0; v < 4; v++) acc[i][f][v] = 0.0f;

    // ---- prologue: issue chunks 0 and 1 ----
#pragma unroll
    for (int c = 0; c < 2; c++) {
        const uint32_t bo = c * BUFSZ;
        const size_t ko = (size_t)c * KCH;
        cpa16(d0 + bo + AH_OFF, hin_hi + a_src0 + ko);
        cpa16(d1 + bo + AH_OFF, hin_hi + a_src1 + ko);
        cpa16(d0 + bo + AL_OFF, hin_lo + a_src0 + ko);
        cpa16(d1 + bo + AL_OFF, hin_lo + a_src1 + ko);
        cpa16(d0 + bo + BH_OFF, wb_hi + b_src0 + ko);
        cpa16(d1 + bo + BH_OFF, wb_hi + b_src1 + ko);
        cpa16(d0 + bo + BL_OFF, wb_lo + b_src0 + ko);
        cpa16(d1 + bo + BL_OFF, wb_lo + b_src1 + ko);
        CPA_COMMIT();
    }
    CPA_WAIT1();
    __syncthreads();

    int buf = 0;
    for (int c = 0; c < 16; c++) {
        // prefetch chunk c+2 into buffer (c+2)%3
        if (c <= 13) {
            const uint32_t bo = ((c + 2) % NBUF) * BUFSZ;
            const size_t ko = (size_t)(c + 2) * KCH;
            cpa16(d0 + bo + AH_OFF, hin_hi + a_src0 + ko);
            cpa16(d1 + bo + AH_OFF, hin_hi + a_src1 + ko);
            cpa16(d0 + bo + AL_OFF, hin_lo + a_src0 + ko);
            cpa16(d1 + bo + AL_OFF, hin_lo + a_src1 + ko);
            cpa16(d0 + bo + BH_OFF, wb_hi + b_src0 + ko);
            cpa16(d1 + bo + BH_OFF, wb_hi + b_src1 + ko);
            cpa16(d0 + bo + BL_OFF, wb_lo + b_src0 + ko);
            cpa16(d1 + bo + BL_OFF, wb_lo + b_src1 + ko);
            CPA_COMMIT();
        }

        const uint32_t base = smem_base + buf * BUFSZ;
#pragma unroll
        for (int s = 0; s < 2; s++) {
            const uint32_t sx = s ? 32u : 0u;
            uint32_t ah[4][4], al[4][4], bb[2][4];
            // A hi + B hi
#pragma unroll
            for (int i = 0; i < 4; i++) ldsm_x4(ah[i], base + AH_OFF + (a_off[i] ^ sx));
#pragma unroll
            for (int q = 0; q < 2; q++) ldsm_x4(bb[q], base + BH_OFF + (b_off[q] ^ sx));
            // pass hh
#pragma unroll
            for (int i = 0; i < 4; i++)
#pragma unroll
                for (int f = 0; f < 4; f++)
                    mma16816(acc[i][f], ah[i], &bb[f >> 1][(f & 1) * 2]);
            // A lo, pass lh (B hi still live)
#pragma unroll
            for (int i = 0; i < 4; i++) ldsm_x4(al[i], base + AL_OFF + (a_off[i] ^ sx));
#pragma unroll
            for (int i = 0; i < 4; i++)
#pragma unroll
                for (int f = 0; f < 4; f++)
                    mma16816(acc[i][f], al[i], &bb[f >> 1][(f & 1) * 2]);
            // B lo (reuse bb regs), pass hl
#pragma unroll
            for (int q = 0; q < 2; q++) ldsm_x4(bb[q], base + BL_OFF + (b_off[q] ^ sx));
#pragma unroll
            for (int i = 0; i < 4; i++)
#pragma unroll
                for (int f = 0; f < 4; f++)
                    mma16816(acc[i][f], ah[i], &bb[f >> 1][(f & 1) * 2]);
        }

        if (c <= 13) {
            CPA_WAIT1();
            __syncthreads();
        } else if (c == 14) {
            CPA_WAIT0();
            __syncthreads();
        }
        buf = (buf + 1 == NBUF) ? 0 : buf + 1;
    }

    // ---- stage accumulators to smem (overwrites dead operand buffers) ----
    __syncthreads();
    {
        const int rr = warp_m * 64 + (lid >> 2);
        const int c0 = warp_n * 32 + (lid & 3) * 2;
#pragma unroll
        for (int i = 0; i < 4; i++)
#pragma unroll
            for (int f = 0; f < 4; f++) {
                int r = rr + i * 16;
                int cc = c0 + f * 8;
                *(float2*)&E[r * EPI_STRIDE + cc]       = make_float2(acc[i][f][0], acc[i][f][1]);
                *(float2*)&E[(r + 8) * EPI_STRIDE + cc] = make_float2(acc[i][f][2], acc[i][f][3]);
            }
    }
    __syncthreads();

    // ---- fused LSTM cell epilogue ----
    {
        const int hcol = tid & 31;
        const int mb = (tid >> 5) * 16;
        const int hcol_g = by * 32 + hcol;
#pragma unroll 4
        for (int j = 0; j < 16; j++) {
            const int m = mb + j;
            const int b = bm * 128 + m;
            const float* xg = g_xg + (size_t)b * GDIM + hcol_g;
            float gi = E[m * EPI_STRIDE + hcol]      + xg[0];
            float gf = E[m * EPI_STRIDE + 32 + hcol] + xg[512];
            float gg = E[m * EPI_STRIDE + 64 + hcol] + xg[1024];
            float go = E[m * EPI_STRIDE + 96 + hcol] + xg[1536];
            const size_t ci = (size_t)b * HDIM + hcol_g;
            float cn = sigm(gf) * g_c[ci] + sigm(gi) * tanh_fast(gg);
            g_c[ci] = cn;
            float hn = sigm(go) * tanh_fast(cn);
            g_hs[((size_t)b * TSTEP + t) * HDIM + hcol_g] = hn;
            __nv_bfloat16 hb = __float2bfloat16_rn(hn);
            float rem = hn - __bfloat162float(hb);
            hout_hi[ci] = hb;
            hout_lo[ci] = __float2bfloat16_rn(rem);
        }
    }
}

// -------- fc: out = relu(hs @ fc_w.T + fc_b) --------------------------------
__global__ __launch_bounds__(256)
void fc_kernel(const float* __restrict__ fc_w,
               const float* __restrict__ fc_b,
               float* __restrict__ out) {
    __shared__ float hsS[16][514];
    const size_t row0 = (size_t)blockIdx.x * 16;
    const int tid = threadIdx.x;

#pragma unroll
    for (int it = 0; it < 16; it++) {
        int i = tid + it * 256;
        int row = i >> 8;
        int cc = (i & 255) * 2;
        float2 v = *(const float2*)(g_hs + (row0 + row) * HDIM + cc);
        *(float2*)&hsS[row][cc] = v;
    }
    __syncthreads();

    const int r = tid & 15;
    const int v0 = (tid >> 4) * 4;
    ull acc[4] = {0ull, 0ull, 0ull, 0ull};
    const float* w0 = fc_w + (size_t)v0 * HDIM;

#pragma unroll 8
    for (int k = 0; k < HDIM; k += 2) {
        ull a = *(const ull*)&hsS[r][k];
        acc[0] = ffma2(a, *(const ull*)(w0 + k),        acc[0]);
        acc[1] = ffma2(a, *(const ull*)(w0 + 512 + k),  acc[1]);
        acc[2] = ffma2(a, *(const ull*)(w0 + 1024 + k), acc[2]);
        acc[3] = ffma2(a, *(const ull*)(w0 + 1536 + k), acc[3]);
    }
#pragma unroll
    for (int j = 0; j < 4; j++) {
        float2 s = up2(acc[j]);
        float v = s.x + s.y + fc_b[v0 + j];
        out[(row0 + r) * VDIM + v0 + j] = fmaxf(v, 0.0f);
    }
}

// ---------------- launch ----------------------------------------------------
extern "C" void kernel_launch(void* const* d_in, const int* in_sizes, int n_in,
                              void* d_out, int out_size) {
    const float* z    = (const float*)d_in[0];
    const float* w_ih = (const float*)d_in[1];
    const float* w_hh = (const float*)d_in[2];
    const float* b_ih = (const float*)d_in[3];
    const float* b_hh = (const float*)d_in[4];
    const float* fc_w = (const float*)d_in[5];
    const float* fc_b = (const float*)d_in[6];
    float* out = (float*)d_out;

    cudaFuncSetAttribute(step_mma, cudaFuncAttributeMaxDynamicSharedMemorySize, SMEM_TOTAL);

    init_kernel<<<(BATCH * HDIM + 255) / 256, 256>>>();
    wprep_kernel<<<(16 * 128 * HDIM + 255) / 256, 256>>>(w_hh);
    pre_kernel<<<dim3(16, 16), 256>>>(z, w_ih, b_ih, b_hh);
    for (int t = 0; t < TSTEP; t++) {
        step_mma<<<dim3(16, 16), 256, SMEM_TOTAL>>>(t);
    }
    fc_kernel<<<(BATCH * TSTEP) / 16, 256>>>(fc_w, fc_b, out);
}